// round 4
// baseline (speedup 1.0000x reference)
#include <cuda_runtime.h>
#include <cuda_bf16.h>
#include <cstdint>

#define BATCH 32
#define CH    512
#define SP    1024

// Scratch (device globals — no allocation allowed)
__device__ float          g_mean[BATCH * CH];
__device__ __nv_bfloat16  g_W  [(size_t)BATCH * CH * CH];   // W[b][j][k] = attn[b][k][j]
__device__ __nv_bfloat16  g_Xb [(size_t)BATCH * CH * SP];   // bf16 copy of x, same layout

// ---------------------------------------------------------------------------
// Kernel 1: fused channel-mean + fp32->bf16 cast. Warp per (b,c) row,
// 8 rows per block. Loads batched first (MLP=8), then convert+reduce.
// ---------------------------------------------------------------------------
__global__ void __launch_bounds__(256) prep_kernel(const float* __restrict__ x) {
    int b  = blockIdx.y;
    int c  = blockIdx.x * 8 + (threadIdx.x >> 5);
    int lane = threadIdx.x & 31;

    const float* row = x + ((size_t)b * CH + c) * SP;
    __nv_bfloat16* orow = g_Xb + ((size_t)b * CH + c) * SP;

    float4 v[8];
    #pragma unroll
    for (int i = 0; i < 8; ++i)
        v[i] = *reinterpret_cast<const float4*>(row + lane * 4 + i * 128);

    float s = 0.0f;
    #pragma unroll
    for (int i = 0; i < 8; ++i) {
        s += (v[i].x + v[i].y) + (v[i].z + v[i].w);
        __nv_bfloat162 lo = __floats2bfloat162_rn(v[i].x, v[i].y);
        __nv_bfloat162 hi = __floats2bfloat162_rn(v[i].z, v[i].w);
        uint2 pk;
        pk.x = *reinterpret_cast<uint32_t*>(&lo);
        pk.y = *reinterpret_cast<uint32_t*>(&hi);
        *reinterpret_cast<uint2*>(orow + lane * 4 + i * 128) = pk;
    }
    #pragma unroll
    for (int o = 16; o > 0; o >>= 1) s += __shfl_xor_sync(0xffffffffu, s, o);
    if (lane == 0) g_mean[b * CH + c] = s * (1.0f / SP);
}

// ---------------------------------------------------------------------------
// Kernel 2: W[b][j][k] = exp(-(m_j - m_k)^2) / Z_j   (softmax over k, bf16).
// score[j,j]==0 is the exact row max, so raw exp == shifted softmax.
// ---------------------------------------------------------------------------
__global__ void __launch_bounds__(256) attn_kernel() {
    int b  = blockIdx.y;
    int jc = blockIdx.x;
    __shared__ float sm[CH];
    for (int i = threadIdx.x; i < CH; i += 256) sm[i] = g_mean[b * CH + i];
    __syncthreads();

    int warp = threadIdx.x >> 5, lane = threadIdx.x & 31;
    for (int jr = 0; jr < 16; ++jr) {
        int j = jc * 128 + warp * 16 + jr;
        float mj = sm[j];
        float e[16];
        float sum = 0.0f;
        #pragma unroll
        for (int kk = 0; kk < 16; ++kk) {
            float d = mj - sm[kk * 32 + lane];
            float v = __expf(-d * d);
            e[kk] = v;
            sum += v;
        }
        #pragma unroll
        for (int o = 16; o > 0; o >>= 1) sum += __shfl_xor_sync(0xffffffffu, sum, o);
        float inv = 1.0f / sum;
        __nv_bfloat16* row = g_W + ((size_t)b * CH + j) * CH;
        #pragma unroll
        for (int kk = 0; kk < 16; ++kk)
            row[kk * 32 + lane] = __float2bfloat16(e[kk] * inv);
    }
}

// ---------------------------------------------------------------------------
// Kernel 3: GEMM  D[j,s] = sum_k W[j,k] * Xb[k,s],  out = relu(x + 0.1*D).
// mma.sync m16n8k16 bf16/fp32. CTA 128x256, BK=64, 4-stage cp.async pipeline.
// 8 warps as 2x4, warp tile 64x64. Padded smem strides: conflict-free ldmatrix.
// ---------------------------------------------------------------------------
#define BM 128
#define BN 256
#define BK 64
#define NSTG 4
#define KT 8                      // CH / BK
#define SA_B 144                  // A smem row stride bytes (mod 128 = 16)
#define SB_B 528                  // B smem row stride bytes (mod 128 = 16)
#define A_ST (BM * SA_B)          // 18432
#define B_ST (BK * SB_B)          // 33792
#define STG_B (A_ST + B_ST)       // 52224
#define GEMM_SMEM (NSTG * STG_B + 128)   // 209024

__device__ __forceinline__ uint32_t cvta_s(const void* p) {
    return (uint32_t)__cvta_generic_to_shared(p);
}

__global__ void __launch_bounds__(256, 1)
gemm_kernel(const float* __restrict__ x, float* __restrict__ out) {
    extern __shared__ char dsm[];
    int b  = blockIdx.z;
    int m0 = blockIdx.y * BM;
    int n0 = blockIdx.x * BN;
    int tid = threadIdx.x, lane = tid & 31, warp = tid >> 5;
    int wm = warp >> 2, wn = warp & 3;

    uint32_t base = (cvta_s(dsm) + 127u) & ~127u;

    const __nv_bfloat16* Wg = g_W  + ((size_t)b * CH + m0) * CH;
    const __nv_bfloat16* Xg = g_Xb + (size_t)b * CH * SP + n0;

    // async copy of one K-stage into buffer stg
    auto issue = [&](int kt, int stg) {
        uint32_t Ab = base + stg * STG_B;
        uint32_t Bb = Ab + A_ST;
        #pragma unroll
        for (int i = 0; i < 4; ++i) {
            int chunk = tid + i * 256;                 // A: 128 rows x 8 chunks
            int r = chunk >> 3, c = chunk & 7;
            const void* src = Wg + (size_t)r * CH + kt * BK + c * 8;
            uint32_t dst = Ab + r * SA_B + c * 16;
            asm volatile("cp.async.cg.shared.global [%0], [%1], 16;"
                         :: "r"(dst), "l"(src));
        }
        #pragma unroll
        for (int i = 0; i < 8; ++i) {
            int chunk = tid + i * 256;                 // B: 64 rows x 32 chunks
            int r = chunk >> 5, c = chunk & 31;
            const void* src = Xg + (size_t)(kt * BK + r) * SP + c * 8;
            uint32_t dst = Bb + r * SB_B + c * 16;
            asm volatile("cp.async.cg.shared.global [%0], [%1], 16;"
                         :: "r"(dst), "l"(src));
        }
        asm volatile("cp.async.commit_group;" ::: "memory");
    };

    float acc[4][8][4];
    #pragma unroll
    for (int i = 0; i < 4; ++i)
        #pragma unroll
        for (int j = 0; j < 8; ++j)
            #pragma unroll
            for (int k = 0; k < 4; ++k) acc[i][j][k] = 0.0f;

    issue(0, 0); issue(1, 1); issue(2, 2);

    for (int kt = 0; kt < KT; ++kt) {
        int stg = kt & (NSTG - 1);
        uint32_t Ab = base + stg * STG_B;
        uint32_t Bb = Ab + A_ST;

        asm volatile("cp.async.wait_group 2;" ::: "memory");
        __syncthreads();
        // safe to refill (kt+3)&3 == (kt-1)&3: all warps finished kt-1 compute
        if (kt + 3 < KT) issue(kt + 3, (kt + 3) & (NSTG - 1));

        #pragma unroll
        for (int kk = 0; kk < BK; kk += 16) {
            uint32_t af[4][4], bf[8][2];
            #pragma unroll
            for (int mi = 0; mi < 4; ++mi) {
                int row = wm * 64 + mi * 16 + (lane & 15);
                int col = kk + ((lane >> 4) << 3);
                uint32_t addr = Ab + row * SA_B + col * 2;
                asm volatile("ldmatrix.sync.aligned.m8n8.x4.shared.b16 {%0,%1,%2,%3}, [%4];"
                             : "=r"(af[mi][0]), "=r"(af[mi][1]), "=r"(af[mi][2]), "=r"(af[mi][3])
                             : "r"(addr));
            }
            #pragma unroll
            for (int ni = 0; ni < 4; ++ni) {
                int row = kk + (lane & 15);
                int col = wn * 64 + ni * 16 + ((lane >> 4) << 3);
                uint32_t addr = Bb + row * SB_B + col * 2;
                uint32_t r0, r1, r2, r3;
                asm volatile("ldmatrix.sync.aligned.m8n8.x4.trans.shared.b16 {%0,%1,%2,%3}, [%4];"
                             : "=r"(r0), "=r"(r1), "=r"(r2), "=r"(r3)
                             : "r"(addr));
                bf[ni * 2][0] = r0;      bf[ni * 2][1] = r1;
                bf[ni * 2 + 1][0] = r2;  bf[ni * 2 + 1][1] = r3;
            }
            #pragma unroll
            for (int mi = 0; mi < 4; ++mi)
                #pragma unroll
                for (int nj = 0; nj < 8; ++nj)
                    asm volatile("mma.sync.aligned.m16n8k16.row.col.f32.bf16.bf16.f32 "
                                 "{%0,%1,%2,%3}, {%4,%5,%6,%7}, {%8,%9}, {%0,%1,%2,%3};"
                                 : "+f"(acc[mi][nj][0]), "+f"(acc[mi][nj][1]),
                                   "+f"(acc[mi][nj][2]), "+f"(acc[mi][nj][3])
                                 : "r"(af[mi][0]), "r"(af[mi][1]), "r"(af[mi][2]), "r"(af[mi][3]),
                                   "r"(bf[nj][0]), "r"(bf[nj][1]));
        }
        __syncthreads();
    }

    // Epilogue: relu(x + 0.1*D), fp32 residual read
    const float* Xr = x   + ((size_t)b * CH) * SP;
    float*       Og = out + ((size_t)b * CH) * SP;
    int g = lane >> 2, t = lane & 3;
    #pragma unroll
    for (int mi = 0; mi < 4; ++mi) {
        #pragma unroll
        for (int h = 0; h < 2; ++h) {
            int row = m0 + wm * 64 + mi * 16 + h * 8 + g;
            #pragma unroll
            for (int nj = 0; nj < 8; ++nj) {
                int col = n0 + wn * 64 + nj * 8 + t * 2;
                size_t idx = (size_t)row * SP + col;
                float2 xv = *reinterpret_cast<const float2*>(Xr + idx);
                float r0 = fmaxf(xv.x + 0.1f * acc[mi][nj][h * 2 + 0], 0.0f);
                float r1 = fmaxf(xv.y + 0.1f * acc[mi][nj][h * 2 + 1], 0.0f);
                *reinterpret_cast<float2*>(Og + idx) = make_float2(r0, r1);
            }
        }
    }
}

// ---------------------------------------------------------------------------
extern "C" void kernel_launch(void* const* d_in, const int* in_sizes, int n_in,
                              void* d_out, int out_size) {
    (void)in_sizes; (void)n_in; (void)out_size;
    const float* x = (const float*)d_in[0];
    float* out = (float*)d_out;

    cudaFuncSetAttribute(gemm_kernel, cudaFuncAttributeMaxDynamicSharedMemorySize, GEMM_SMEM);

    prep_kernel<<<dim3(CH / 8, BATCH), 256>>>(x);
    attn_kernel<<<dim3(4, BATCH), 256>>>();
    gemm_kernel<<<dim3(SP / BN, CH / BM, BATCH), 256, GEMM_SMEM>>>(x, out);
}

// round 5
// speedup vs baseline: 1.1756x; 1.1756x over previous
#include <cuda_runtime.h>
#include <cuda_bf16.h>
#include <cstdint>

#define BATCH 32
#define CH    512
#define SP    1024

// Scratch (device globals — no allocation allowed)
__device__ float          g_mean[BATCH * CH];
__device__ __nv_bfloat16  g_W  [(size_t)BATCH * CH * CH];   // W[b][j][k] = attn[b][k][j]
__device__ __nv_bfloat16  g_Xb [(size_t)BATCH * CH * SP];   // bf16 copy of x, same layout

// ---------------------------------------------------------------------------
// Kernel 1: fused channel-mean + fp32->bf16 cast. Warp per (b,c) row,
// 8 rows per block. Loads batched first (MLP=8), then convert+reduce.
// ---------------------------------------------------------------------------
__global__ void __launch_bounds__(256) prep_kernel(const float* __restrict__ x) {
    int b  = blockIdx.y;
    int c  = blockIdx.x * 8 + (threadIdx.x >> 5);
    int lane = threadIdx.x & 31;

    const float* row = x + ((size_t)b * CH + c) * SP;
    __nv_bfloat16* orow = g_Xb + ((size_t)b * CH + c) * SP;

    float4 v[8];
    #pragma unroll
    for (int i = 0; i < 8; ++i)
        v[i] = *reinterpret_cast<const float4*>(row + lane * 4 + i * 128);

    float s = 0.0f;
    #pragma unroll
    for (int i = 0; i < 8; ++i) {
        s += (v[i].x + v[i].y) + (v[i].z + v[i].w);
        __nv_bfloat162 lo = __floats2bfloat162_rn(v[i].x, v[i].y);
        __nv_bfloat162 hi = __floats2bfloat162_rn(v[i].z, v[i].w);
        uint2 pk;
        pk.x = *reinterpret_cast<uint32_t*>(&lo);
        pk.y = *reinterpret_cast<uint32_t*>(&hi);
        *reinterpret_cast<uint2*>(orow + lane * 4 + i * 128) = pk;
    }
    #pragma unroll
    for (int o = 16; o > 0; o >>= 1) s += __shfl_xor_sync(0xffffffffu, s, o);
    if (lane == 0) g_mean[b * CH + c] = s * (1.0f / SP);
}

// ---------------------------------------------------------------------------
// Kernel 2: W[b][j][k] = exp(-(m_j - m_k)^2) / Z_j   (softmax over k, bf16).
// score[j,j]==0 is the exact row max, so raw exp == shifted softmax.
// ---------------------------------------------------------------------------
__global__ void __launch_bounds__(256) attn_kernel() {
    int b  = blockIdx.y;
    int jc = blockIdx.x;
    __shared__ float sm[CH];
    for (int i = threadIdx.x; i < CH; i += 256) sm[i] = g_mean[b * CH + i];
    __syncthreads();

    int warp = threadIdx.x >> 5, lane = threadIdx.x & 31;
    for (int jr = 0; jr < 16; ++jr) {
        int j = jc * 128 + warp * 16 + jr;
        float mj = sm[j];
        float e[16];
        float sum = 0.0f;
        #pragma unroll
        for (int kk = 0; kk < 16; ++kk) {
            float d = mj - sm[kk * 32 + lane];
            float v = __expf(-d * d);
            e[kk] = v;
            sum += v;
        }
        #pragma unroll
        for (int o = 16; o > 0; o >>= 1) sum += __shfl_xor_sync(0xffffffffu, sum, o);
        float inv = 1.0f / sum;
        __nv_bfloat16* row = g_W + ((size_t)b * CH + j) * CH;
        #pragma unroll
        for (int kk = 0; kk < 16; ++kk)
            row[kk * 32 + lane] = __float2bfloat16(e[kk] * inv);
    }
}

// ---------------------------------------------------------------------------
// Kernel 3: GEMM  D[j,s] = sum_k W[j,k] * Xb[k,s],  out = relu(x + 0.1*D).
// mma.sync m16n8k16 bf16/fp32. CTA 128x128, BK=64, 3-stage cp.async pipeline,
// 2 CTAs/SM (16 warps) for latency hiding. 8 warps as 2x4, warp tile 64x32.
// ---------------------------------------------------------------------------
#define BM 128
#define BN 128
#define BK 64
#define NSTG 3
#define KT 8                      // CH / BK
#define SA_B 144                  // A smem row stride bytes (mod 128 = 16)
#define SB_B 272                  // B smem row stride bytes (mod 128 = 16)
#define A_ST (BM * SA_B)          // 18432
#define B_ST (BK * SB_B)          // 17408
#define STG_B (A_ST + B_ST)       // 35840
#define GEMM_SMEM (NSTG * STG_B + 128)   // 107648

__device__ __forceinline__ uint32_t cvta_s(const void* p) {
    return (uint32_t)__cvta_generic_to_shared(p);
}

__global__ void __launch_bounds__(256, 2)
gemm_kernel(const float* __restrict__ x, float* __restrict__ out) {
    extern __shared__ char dsm[];
    int b  = blockIdx.z;
    int m0 = blockIdx.y * BM;
    int n0 = blockIdx.x * BN;
    int tid = threadIdx.x, lane = tid & 31, warp = tid >> 5;
    int wm = warp >> 2, wn = warp & 3;

    uint32_t base = (cvta_s(dsm) + 127u) & ~127u;

    const __nv_bfloat16* Wg = g_W  + ((size_t)b * CH + m0) * CH;
    const __nv_bfloat16* Xg = g_Xb + (size_t)b * CH * SP + n0;

    // async copy of one K-stage into buffer stg
    auto issue = [&](int kt, int stg) {
        uint32_t Ab = base + stg * STG_B;
        uint32_t Bb = Ab + A_ST;
        #pragma unroll
        for (int i = 0; i < 4; ++i) {
            int chunk = tid + i * 256;                 // A: 128 rows x 8 chunks
            int r = chunk >> 3, c = chunk & 7;
            const void* src = Wg + (size_t)r * CH + kt * BK + c * 8;
            uint32_t dst = Ab + r * SA_B + c * 16;
            asm volatile("cp.async.cg.shared.global [%0], [%1], 16;"
                         :: "r"(dst), "l"(src));
        }
        #pragma unroll
        for (int i = 0; i < 4; ++i) {
            int chunk = tid + i * 256;                 // B: 64 rows x 16 chunks
            int r = chunk >> 4, c = chunk & 15;
            const void* src = Xg + (size_t)(kt * BK + r) * SP + c * 8;
            uint32_t dst = Bb + r * SB_B + c * 16;
            asm volatile("cp.async.cg.shared.global [%0], [%1], 16;"
                         :: "r"(dst), "l"(src));
        }
        asm volatile("cp.async.commit_group;" ::: "memory");
    };

    float acc[4][4][4];
    #pragma unroll
    for (int i = 0; i < 4; ++i)
        #pragma unroll
        for (int j = 0; j < 4; ++j)
            #pragma unroll
            for (int k = 0; k < 4; ++k) acc[i][j][k] = 0.0f;

    issue(0, 0); issue(1, 1);

    for (int kt = 0; kt < KT; ++kt) {
        int stg = kt % NSTG;
        uint32_t Ab = base + stg * STG_B;
        uint32_t Bb = Ab + A_ST;

        asm volatile("cp.async.wait_group 1;" ::: "memory");
        __syncthreads();
        // refill buffer (kt+2)%3 == (kt-1)%3: consumed at kt-1, bottom sync done
        if (kt + 2 < KT) issue(kt + 2, (kt + 2) % NSTG);

        #pragma unroll
        for (int kk = 0; kk < BK; kk += 16) {
            uint32_t af[4][4], bf[4][2];
            #pragma unroll
            for (int mi = 0; mi < 4; ++mi) {
                int row = wm * 64 + mi * 16 + (lane & 15);
                int col = kk + ((lane >> 4) << 3);
                uint32_t addr = Ab + row * SA_B + col * 2;
                asm volatile("ldmatrix.sync.aligned.m8n8.x4.shared.b16 {%0,%1,%2,%3}, [%4];"
                             : "=r"(af[mi][0]), "=r"(af[mi][1]), "=r"(af[mi][2]), "=r"(af[mi][3])
                             : "r"(addr));
            }
            #pragma unroll
            for (int ni = 0; ni < 2; ++ni) {
                int row = kk + (lane & 15);
                int col = wn * 32 + ni * 16 + ((lane >> 4) << 3);
                uint32_t addr = Bb + row * SB_B + col * 2;
                uint32_t r0, r1, r2, r3;
                asm volatile("ldmatrix.sync.aligned.m8n8.x4.trans.shared.b16 {%0,%1,%2,%3}, [%4];"
                             : "=r"(r0), "=r"(r1), "=r"(r2), "=r"(r3)
                             : "r"(addr));
                bf[ni * 2][0] = r0;      bf[ni * 2][1] = r1;
                bf[ni * 2 + 1][0] = r2;  bf[ni * 2 + 1][1] = r3;
            }
            #pragma unroll
            for (int mi = 0; mi < 4; ++mi)
                #pragma unroll
                for (int nj = 0; nj < 4; ++nj)
                    asm volatile("mma.sync.aligned.m16n8k16.row.col.f32.bf16.bf16.f32 "
                                 "{%0,%1,%2,%3}, {%4,%5,%6,%7}, {%8,%9}, {%0,%1,%2,%3};"
                                 : "+f"(acc[mi][nj][0]), "+f"(acc[mi][nj][1]),
                                   "+f"(acc[mi][nj][2]), "+f"(acc[mi][nj][3])
                                 : "r"(af[mi][0]), "r"(af[mi][1]), "r"(af[mi][2]), "r"(af[mi][3]),
                                   "r"(bf[nj][0]), "r"(bf[nj][1]));
        }
        __syncthreads();
    }

    // Epilogue: relu(x + 0.1*D), fp32 residual read
    const float* Xr = x   + ((size_t)b * CH) * SP;
    float*       Og = out + ((size_t)b * CH) * SP;
    int g = lane >> 2, t = lane & 3;
    #pragma unroll
    for (int mi = 0; mi < 4; ++mi) {
        #pragma unroll
        for (int h = 0; h < 2; ++h) {
            int row = m0 + wm * 64 + mi * 16 + h * 8 + g;
            #pragma unroll
            for (int nj = 0; nj < 4; ++nj) {
                int col = n0 + wn * 32 + nj * 8 + t * 2;
                size_t idx = (size_t)row * SP + col;
                float2 xv = *reinterpret_cast<const float2*>(Xr + idx);
                float r0 = fmaxf(xv.x + 0.1f * acc[mi][nj][h * 2 + 0], 0.0f);
                float r1 = fmaxf(xv.y + 0.1f * acc[mi][nj][h * 2 + 1], 0.0f);
                *reinterpret_cast<float2*>(Og + idx) = make_float2(r0, r1);
            }
        }
    }
}

// ---------------------------------------------------------------------------
extern "C" void kernel_launch(void* const* d_in, const int* in_sizes, int n_in,
                              void* d_out, int out_size) {
    (void)in_sizes; (void)n_in; (void)out_size;
    const float* x = (const float*)d_in[0];
    float* out = (float*)d_out;

    cudaFuncSetAttribute(gemm_kernel, cudaFuncAttributeMaxDynamicSharedMemorySize, GEMM_SMEM);

    prep_kernel<<<dim3(CH / 8, BATCH), 256>>>(x);
    attn_kernel<<<dim3(4, BATCH), 256>>>();
    gemm_kernel<<<dim3(SP / BN, CH / BM, BATCH), 256, GEMM_SMEM>>>(x, out);
}

// round 6
// speedup vs baseline: 1.2734x; 1.0832x over previous
#include <cuda_runtime.h>
#include <cuda_bf16.h>
#include <cstdint>

#define BATCH 32
#define CH    512
#define SP    1024

// Scratch (device globals — no allocation allowed)
__device__ float          g_mean[BATCH * CH];
__device__ __nv_bfloat16  g_W  [(size_t)BATCH * CH * CH];   // W[b][j][k] = attn[b][k][j]
__device__ __nv_bfloat16  g_Xb [(size_t)BATCH * CH * SP];   // bf16 copy of x, same layout

// ---------------------------------------------------------------------------
// Kernel 1: fused channel-mean + fp32->bf16 cast. Warp per (b,c) row,
// 8 rows per block. Loads batched first (MLP=8), then convert+reduce.
// ---------------------------------------------------------------------------
__global__ void __launch_bounds__(256) prep_kernel(const float* __restrict__ x) {
    int b  = blockIdx.y;
    int c  = blockIdx.x * 8 + (threadIdx.x >> 5);
    int lane = threadIdx.x & 31;

    const float* row = x + ((size_t)b * CH + c) * SP;
    __nv_bfloat16* orow = g_Xb + ((size_t)b * CH + c) * SP;

    float4 v[8];
    #pragma unroll
    for (int i = 0; i < 8; ++i)
        v[i] = *reinterpret_cast<const float4*>(row + lane * 4 + i * 128);

    float s = 0.0f;
    #pragma unroll
    for (int i = 0; i < 8; ++i) {
        s += (v[i].x + v[i].y) + (v[i].z + v[i].w);
        __nv_bfloat162 lo = __floats2bfloat162_rn(v[i].x, v[i].y);
        __nv_bfloat162 hi = __floats2bfloat162_rn(v[i].z, v[i].w);
        uint2 pk;
        pk.x = *reinterpret_cast<uint32_t*>(&lo);
        pk.y = *reinterpret_cast<uint32_t*>(&hi);
        *reinterpret_cast<uint2*>(orow + lane * 4 + i * 128) = pk;
    }
    #pragma unroll
    for (int o = 16; o > 0; o >>= 1) s += __shfl_xor_sync(0xffffffffu, s, o);
    if (lane == 0) g_mean[b * CH + c] = s * (1.0f / SP);
}

// ---------------------------------------------------------------------------
// Kernel 2: W[b][j][k] = exp(-(m_j - m_k)^2) / Z_j   (softmax over k, bf16).
// score[j,j]==0 is the exact row max, so raw exp == shifted softmax.
// ---------------------------------------------------------------------------
__global__ void __launch_bounds__(256) attn_kernel() {
    int b  = blockIdx.y;
    int jc = blockIdx.x;
    __shared__ float sm[CH];
    for (int i = threadIdx.x; i < CH; i += 256) sm[i] = g_mean[b * CH + i];
    __syncthreads();

    int warp = threadIdx.x >> 5, lane = threadIdx.x & 31;
    for (int jr = 0; jr < 16; ++jr) {
        int j = jc * 128 + warp * 16 + jr;
        float mj = sm[j];
        float e[16];
        float sum = 0.0f;
        #pragma unroll
        for (int kk = 0; kk < 16; ++kk) {
            float d = mj - sm[kk * 32 + lane];
            float v = __expf(-d * d);
            e[kk] = v;
            sum += v;
        }
        #pragma unroll
        for (int o = 16; o > 0; o >>= 1) sum += __shfl_xor_sync(0xffffffffu, sum, o);
        float inv = 1.0f / sum;
        __nv_bfloat16* row = g_W + ((size_t)b * CH + j) * CH;
        #pragma unroll
        for (int kk = 0; kk < 16; ++kk)
            row[kk * 32 + lane] = __float2bfloat16(e[kk] * inv);
    }
}

// ---------------------------------------------------------------------------
// Kernel 3: GEMM  D[j,s] = sum_k W[j,k] * Xb[k,s],  out = relu(x + 0.1*D).
// mma.sync m16n8k16 bf16/fp32. CTA 128x128, BK=32, 5-stage cp.async pipeline
// (prefetch depth 4), 2 CTAs/SM, ONE barrier per mainloop iteration.
// 8 warps as 2x4, warp tile 64x32.
// ---------------------------------------------------------------------------
#define BM 128
#define BN 128
#define BK 32
#define NSTG 5
#define KT 16                     // CH / BK
#define SA_B 80                   // A smem row stride bytes (mod 128 = 80, conflict-free)
#define SB_B 272                  // B smem row stride bytes (mod 128 = 16, conflict-free)
#define A_ST (BM * SA_B)          // 10240
#define B_ST (BK * SB_B)          // 8704
#define STG_B (A_ST + B_ST)       // 18944
#define GEMM_SMEM (NSTG * STG_B + 128)   // 94848

__device__ __forceinline__ uint32_t cvta_s(const void* p) {
    return (uint32_t)__cvta_generic_to_shared(p);
}

__global__ void __launch_bounds__(256, 2)
gemm_kernel(const float* __restrict__ x, float* __restrict__ out) {
    extern __shared__ char dsm[];
    int b  = blockIdx.z;
    int m0 = blockIdx.y * BM;
    int n0 = blockIdx.x * BN;
    int tid = threadIdx.x, lane = tid & 31, warp = tid >> 5;
    int wm = warp >> 2, wn = warp & 3;

    uint32_t base = (cvta_s(dsm) + 127u) & ~127u;

    const __nv_bfloat16* Wg = g_W  + ((size_t)b * CH + m0) * CH;
    const __nv_bfloat16* Xg = g_Xb + (size_t)b * CH * SP + n0;

    // async copy of one K-stage (BK=32) into buffer stg
    auto issue = [&](int kt, int stg) {
        uint32_t Ab = base + stg * STG_B;
        uint32_t Bb = Ab + A_ST;
        #pragma unroll
        for (int i = 0; i < 2; ++i) {
            int chunk = tid + i * 256;                 // A: 128 rows x 4 chunks
            int r = chunk >> 2, c = chunk & 3;
            const void* src = Wg + (size_t)r * CH + kt * BK + c * 8;
            uint32_t dst = Ab + r * SA_B + c * 16;
            asm volatile("cp.async.cg.shared.global [%0], [%1], 16;"
                         :: "r"(dst), "l"(src));
        }
        #pragma unroll
        for (int i = 0; i < 2; ++i) {
            int chunk = tid + i * 256;                 // B: 32 rows x 16 chunks
            int r = chunk >> 4, c = chunk & 15;
            const void* src = Xg + (size_t)(kt * BK + r) * SP + c * 8;
            uint32_t dst = Bb + r * SB_B + c * 16;
            asm volatile("cp.async.cg.shared.global [%0], [%1], 16;"
                         :: "r"(dst), "l"(src));
        }
        asm volatile("cp.async.commit_group;" ::: "memory");
    };

    float acc[4][4][4];
    #pragma unroll
    for (int i = 0; i < 4; ++i)
        #pragma unroll
        for (int j = 0; j < 4; ++j)
            #pragma unroll
            for (int k = 0; k < 4; ++k) acc[i][j][k] = 0.0f;

    issue(0, 0); issue(1, 1); issue(2, 2); issue(3, 3);

    for (int kt = 0; kt < KT; ++kt) {
        int stg = kt % NSTG;
        uint32_t Ab = base + stg * STG_B;
        uint32_t Bb = Ab + A_ST;

        asm volatile("cp.async.wait_group 3;" ::: "memory");
        __syncthreads();
        // refill (kt+4)%5 == (kt-1)%5: consumed at kt-1, all warps past the
        // barrier above have finished kt-1 — safe, no second barrier needed.
        if (kt + 4 < KT) issue(kt + 4, (kt + 4) % NSTG);

        #pragma unroll
        for (int kk = 0; kk < BK; kk += 16) {
            uint32_t af[4][4], bf[4][2];
            #pragma unroll
            for (int mi = 0; mi < 4; ++mi) {
                int row = wm * 64 + mi * 16 + (lane & 15);
                int col = kk + ((lane >> 4) << 3);
                uint32_t addr = Ab + row * SA_B + col * 2;
                asm volatile("ldmatrix.sync.aligned.m8n8.x4.shared.b16 {%0,%1,%2,%3}, [%4];"
                             : "=r"(af[mi][0]), "=r"(af[mi][1]), "=r"(af[mi][2]), "=r"(af[mi][3])
                             : "r"(addr));
            }
            #pragma unroll
            for (int ni = 0; ni < 2; ++ni) {
                int row = kk + (lane & 15);
                int col = wn * 32 + ni * 16 + ((lane >> 4) << 3);
                uint32_t addr = Bb + row * SB_B + col * 2;
                uint32_t r0, r1, r2, r3;
                asm volatile("ldmatrix.sync.aligned.m8n8.x4.trans.shared.b16 {%0,%1,%2,%3}, [%4];"
                             : "=r"(r0), "=r"(r1), "=r"(r2), "=r"(r3)
                             : "r"(addr));
                bf[ni * 2][0] = r0;      bf[ni * 2][1] = r1;
                bf[ni * 2 + 1][0] = r2;  bf[ni * 2 + 1][1] = r3;
            }
            #pragma unroll
            for (int mi = 0; mi < 4; ++mi)
                #pragma unroll
                for (int nj = 0; nj < 4; ++nj)
                    asm volatile("mma.sync.aligned.m16n8k16.row.col.f32.bf16.bf16.f32 "
                                 "{%0,%1,%2,%3}, {%4,%5,%6,%7}, {%8,%9}, {%0,%1,%2,%3};"
                                 : "+f"(acc[mi][nj][0]), "+f"(acc[mi][nj][1]),
                                   "+f"(acc[mi][nj][2]), "+f"(acc[mi][nj][3])
                                 : "r"(af[mi][0]), "r"(af[mi][1]), "r"(af[mi][2]), "r"(af[mi][3]),
                                   "r"(bf[nj][0]), "r"(bf[nj][1]));
        }
    }

    // Epilogue: relu(x + 0.1*D), fp32 residual read
    const float* Xr = x   + ((size_t)b * CH) * SP;
    float*       Og = out + ((size_t)b * CH) * SP;
    int g = lane >> 2, t = lane & 3;
    #pragma unroll
    for (int mi = 0; mi < 4; ++mi) {
        #pragma unroll
        for (int h = 0; h < 2; ++h) {
            int row = m0 + wm * 64 + mi * 16 + h * 8 + g;
            #pragma unroll
            for (int nj = 0; nj < 4; ++nj) {
                int col = n0 + wn * 32 + nj * 8 + t * 2;
                size_t idx = (size_t)row * SP + col;
                float2 xv = *reinterpret_cast<const float2*>(Xr + idx);
                float r0 = fmaxf(xv.x + 0.1f * acc[mi][nj][h * 2 + 0], 0.0f);
                float r1 = fmaxf(xv.y + 0.1f * acc[mi][nj][h * 2 + 1], 0.0f);
                *reinterpret_cast<float2*>(Og + idx) = make_float2(r0, r1);
            }
        }
    }
}

// ---------------------------------------------------------------------------
extern "C" void kernel_launch(void* const* d_in, const int* in_sizes, int n_in,
                              void* d_out, int out_size) {
    (void)in_sizes; (void)n_in; (void)out_size;
    const float* x = (const float*)d_in[0];
    float* out = (float*)d_out;

    cudaFuncSetAttribute(gemm_kernel, cudaFuncAttributeMaxDynamicSharedMemorySize, GEMM_SMEM);

    prep_kernel<<<dim3(CH / 8, BATCH), 256>>>(x);
    attn_kernel<<<dim3(4, BATCH), 256>>>();
    gemm_kernel<<<dim3(SP / BN, CH / BM, BATCH), 256, GEMM_SMEM>>>(x, out);
}